// round 14
// baseline (speedup 1.0000x reference)
#include <cuda_runtime.h>
#include <cuda_fp16.h>
#include <math.h>
#include <stdint.h>

#define NB    16
#define H8    44
#define W8    144
#define HWLO  (H8 * W8)        // 6336
#define NPIX  (NB * HWLO)      // 101376
#define HOUT  (H8 * 8)         // 352
#define WOUT  (W8 * 8)         // 1152
#define P     128              // pixels per tile
#define NTILES (NPIX / P)      // 792
#define NTHR  256
#define PI_F  3.1415926535f
#define MAX_DEPTH 81.0f

typedef unsigned long long u64;

// ---- smem layout (u32/float offsets) — permuted fragment regions ----
// Region A (32KB): Xp [nq4][kb8][lid32][j8] u32 (f16x2)  -> alias a1p (same dims, f32)
//                                                        -> alias pln [4][128] f32
// Region B (16KB): W0p [mg2][kb8][lid32][j8] u32 (f16x2) -> alias a2p [wid8][k0 4][lid32][j4] f32
// Region C (4KB):  a3h  __half [128 px][16]
#define OFF_XP    0
#define OFF_A1P   0
#define OFF_PLN   0
#define OFF_W0P   8192
#define OFF_A2P   8192
#define OFF_A3H   12288        // 1024 u32 = 2048 halves
#define OFF_WT3   13312        // 128
#define OFF_WT4   13440        // 32
#define OFF_WC    13472        // 16
#define OFF_B0    13488        // 64
#define OFF_B1    13552        // 32
#define OFF_B2    13584        // 16
#define OFF_B3    13600        // 8
#define OFF_B4    13608        // 4
#define OFF_BC    13612        // 4
#define SMEM_FLOATS 13616
#define SMEM_BYTES  (SMEM_FLOATS * 4)   // 54464 B -> 4 CTAs/SM

// ---------------- helpers -------------------------------------------------------
__device__ __forceinline__ uint32_t h2(float lo, float hi) {
    uint32_t r; asm("cvt.rn.f16x2.f32 %0, %1, %2;" : "=r"(r) : "f"(hi), "f"(lo)); return r;
}
__device__ __forceinline__ u64 pack2(float lo, float hi) {
    u64 r; asm("mov.b64 %0, {%1, %2};" : "=l"(r) : "f"(lo), "f"(hi)); return r;
}
__device__ __forceinline__ void unpack2(u64 v, float& lo, float& hi) {
    asm("mov.b64 {%0, %1}, %2;" : "=f"(lo), "=f"(hi) : "l"(v));
}
__device__ __forceinline__ u64 fma2(u64 a, u64 b, u64 c) {
    u64 d; asm("fma.rn.f32x2 %0, %1, %2, %3;" : "=l"(d) : "l"(a), "l"(b), "l"(c));
    return d;
}
__device__ __forceinline__ float eluf(float v) {
    return fmaxf(v, 0.0f) + (__expf(fminf(v, 0.0f)) - 1.0f);
}
__device__ __forceinline__ float sigmoidf_fast(float v) {
    return __fdividef(1.0f, 1.0f + __expf(-v));
}
__device__ __forceinline__ void mma16f(float* d, uint32_t a0, uint32_t a1, uint32_t a2,
                                       uint32_t a3, uint32_t b0, uint32_t b1) {
    asm volatile(
        "mma.sync.aligned.m16n8k16.row.col.f32.f16.f16.f32 "
        "{%0,%1,%2,%3}, {%4,%5,%6,%7}, {%8,%9}, {%0,%1,%2,%3};"
        : "+f"(d[0]), "+f"(d[1]), "+f"(d[2]), "+f"(d[3])
        : "r"(a0), "r"(a1), "r"(a2), "r"(a3), "r"(b0), "r"(b1));
}
__device__ __forceinline__ void mma8(float* d, uint32_t a0, uint32_t a1, uint32_t a2,
                                     uint32_t a3, uint32_t b0, uint32_t b1) {
    asm volatile(
        "mma.sync.aligned.m16n8k8.row.col.f32.tf32.tf32.f32 "
        "{%0,%1,%2,%3}, {%4,%5,%6,%7}, {%8,%9}, {%0,%1,%2,%3};"
        : "+f"(d[0]), "+f"(d[1]), "+f"(d[2]), "+f"(d[3])
        : "r"(a0), "r"(a1), "r"(a2), "r"(a3), "r"(b0), "r"(b1));
}

// ---------------------------------- kernel ------------------------------------
__global__ __launch_bounds__(NTHR, 4) void lpg_mma_kernel(
    const float* __restrict__ x,
    const float* __restrict__ w0, const float* __restrict__ b0,
    const float* __restrict__ w1, const float* __restrict__ b1,
    const float* __restrict__ w2, const float* __restrict__ b2,
    const float* __restrict__ w3, const float* __restrict__ b3,
    const float* __restrict__ w4, const float* __restrict__ b4,
    const float* __restrict__ wc, const float* __restrict__ bc,
    float* __restrict__ out)
{
    extern __shared__ float sm[];
    uint32_t* Xp  = (uint32_t*)(sm + OFF_XP);
    uint32_t* W0p = (uint32_t*)(sm + OFF_W0P);
    uint32_t* a1p = (uint32_t*)(sm + OFF_A1P);
    uint32_t* a2p = (uint32_t*)(sm + OFF_A2P);
    __half*   a3h = (__half*)(sm + OFF_A3H);
    float*    pln = sm + OFF_PLN;
    float* wT3 = sm + OFF_WT3;
    float* wT4 = sm + OFF_WT4;
    float* sWc = sm + OFF_WC;
    float* sB0 = sm + OFF_B0;
    float* sB1 = sm + OFF_B1;
    float* sB2 = sm + OFF_B2;
    float* sB3 = sm + OFF_B3;
    float* sB4 = sm + OFF_B4;
    float* sBc = sm + OFF_BC;

    const int t   = threadIdx.x;
    const int wid = t >> 5;
    const int lid = t & 31;
    const int p0  = blockIdx.x * P;
    const int g   = lid >> 2;      // MMA groupID
    const int r   = lid & 3;       // MMA threadID-in-group

    // ---- stage X: [128ch][128px] -> permuted f16x2 fragments -----------------------
    {
        const int q4  = t & 31;               // 4-pixel group
        const int cp0 = t >> 5;               // channel-pair within k-chunk (0..7)
        const int p   = p0 + 4 * q4;
        const int bb  = p / HWLO;
        const int hw  = p - bb * HWLO;
        const float* __restrict__ xb = x + ((size_t)bb * 128) * HWLO + hw;
        // invariant dest parts
        const int rr  = cp0 & 3;
        const int hh  = (cp0 >= 4) ? 1 : 0;
        const int nq  = q4 >> 3;
        const int nn  = (q4 >> 1) & 3;
        const int gb  = 4 * (q4 & 1);
        const int jj  = nn * 2 + hh;
#pragma unroll
        for (int i = 0; i < 8; i++) {          // i = kb
            const int cpair = cp0 + 8 * i;
            const float4 v0 = __ldg((const float4*)(xb + (size_t)(2 * cpair) * HWLO));
            const float4 v1 = __ldg((const float4*)(xb + (size_t)(2 * cpair + 1) * HWLO));
            uint32_t* base = Xp + ((nq * 8 + i) * 32) * 8 + rr * 8 + jj;
            base[(gb + 0) * 32] = h2(v0.x, v1.x);
            base[(gb + 1) * 32] = h2(v0.y, v1.y);
            base[(gb + 2) * 32] = h2(v0.z, v1.z);
            base[(gb + 3) * 32] = h2(v0.w, v1.w);
        }
    }
    // ---- stage W0: [64][128] -> permuted f16x2 A-fragments --------------------------
#pragma unroll
    for (int ii = 0; ii < 4; ii++) {
        const int idx = t + ii * 256;          // 0..1023
        const int o = idx >> 4, q = idx & 15;  // row, 4-kpair block
        const float4 va = __ldg((const float4*)(w0 + o * 128 + 8 * q));
        const float4 vb = __ldg((const float4*)(w0 + o * 128 + 8 * q + 4));
        const int mg = o >> 5, mo = o & 31;
        const int gg = mo & 7, m8 = mo >> 3;
        const int kb = q >> 1;
        const int hh = q & 1;
        const int jw = (m8 >> 1) * 4 + hh * 2 + (m8 & 1);
        uint32_t* base = W0p + ((mg * 8 + kb) * 32 + gg * 4) * 8 + jw;
        base[0 * 8] = h2(va.x, va.y);
        base[1 * 8] = h2(va.z, va.w);
        base[2 * 8] = h2(vb.x, vb.y);
        base[3 * 8] = h2(vb.z, vb.w);
    }
    // ---- small tables ----------------------------------------------------------------
    if (t < 128) { int o = t >> 4, c = t & 15; wT3[c * 8 + o] = w3[t]; }
    if (t < 32)  { int o = t >> 3, c = t & 7;  wT4[c * 4 + o] = w4[t]; }
    if (t < 12)  { int o = t >> 2, c = t & 3;  sWc[c * 3 + o] = wc[t]; }
    if (t < 64) sB0[t] = b0[t];
    if (t < 32) sB1[t] = b1[t];
    if (t < 16) sB2[t] = b2[t];
    if (t < 8)  sB3[t] = b3[t];
    if (t < 4)  sB4[t] = b4[t];
    if (t < 3)  sBc[t] = bc[t];
    __syncthreads();

    // ============ layer 1 (f16 k16): D[64][128] = W0 x X ============================
    const int mg = wid & 1;
    const int nq = wid >> 1;
    float d0[4][4], d1[4][4];
#pragma unroll
    for (int n = 0; n < 4; n++) {
        d0[n][0] = d0[n][1] = d0[n][2] = d0[n][3] = 0.0f;
        d1[n][0] = d1[n][1] = d1[n][2] = d1[n][3] = 0.0f;
    }
#pragma unroll
    for (int kb = 0; kb < 8; kb++) {
        const uint32_t* ap = W0p + ((mg * 8 + kb) * 32 + lid) * 8;
        const uint32_t* bp = Xp  + ((nq * 8 + kb) * 32 + lid) * 8;
        const uint4 A0 = *(const uint4*)ap;
        const uint4 A1 = *(const uint4*)(ap + 4);
        const uint4 B0 = *(const uint4*)bp;
        const uint4 B1 = *(const uint4*)(bp + 4);
        mma16f(d0[0], A0.x, A0.y, A0.z, A0.w, B0.x, B0.y);
        mma16f(d0[1], A0.x, A0.y, A0.z, A0.w, B0.z, B0.w);
        mma16f(d0[2], A0.x, A0.y, A0.z, A0.w, B1.x, B1.y);
        mma16f(d0[3], A0.x, A0.y, A0.z, A0.w, B1.z, B1.w);
        mma16f(d1[0], A1.x, A1.y, A1.z, A1.w, B0.x, B0.y);
        mma16f(d1[1], A1.x, A1.y, A1.z, A1.w, B0.z, B0.w);
        mma16f(d1[2], A1.x, A1.y, A1.z, A1.w, B1.x, B1.y);
        mma16f(d1[3], A1.x, A1.y, A1.z, A1.w, B1.z, B1.w);
    }
    __syncthreads();            // Xp dead -> a1p (alias) writable

    // ---- a1 scatter directly into L2 B-fragment layout (f32/tf32) -------------------
    {
        const int row0 = mg * 32 + g;
        const float bzA = sB0[row0],      bzB = sB0[row0 + 8];
        const float bzC = sB0[row0 + 16], bzD = sB0[row0 + 24];
        const int lidb = (2 * r) * 4 + (g & 3);
        const int hb   = (g >= 4) ? 1 : 0;
#pragma unroll
        for (int n = 0; n < 4; n++) {
            const int jv = n * 2 + hb;
#pragma unroll
            for (int o8 = 0; o8 < 4; o8++) {
                float v0, v1, bz;
                if (o8 == 0)      { v0 = d0[n][0]; v1 = d0[n][1]; bz = bzA; }
                else if (o8 == 1) { v0 = d0[n][2]; v1 = d0[n][3]; bz = bzB; }
                else if (o8 == 2) { v0 = d1[n][0]; v1 = d1[n][1]; bz = bzC; }
                else              { v0 = d1[n][2]; v1 = d1[n][3]; bz = bzD; }
                uint32_t* base = a1p + ((nq * 8 + mg * 4 + o8) * 32 + lidb) * 8 + jv;
                base[0]  = __float_as_uint(eluf(v0 + bz));
                base[32] = __float_as_uint(eluf(v1 + bz));   // delta=1 -> lid+4 -> +32
            }
        }
    }
    __syncthreads();

    // ============ layer 2 (tf32 k8): D[32][128] = W1 x a1 ============================
    {
        const int rb = wid & 1;
        const int wq = wid >> 1;
        float d[4][4];
#pragma unroll
        for (int n = 0; n < 4; n++) { d[n][0] = d[n][1] = d[n][2] = d[n][3] = 0.0f; }
        const float* w1r0 = w1 + (rb * 16 + g) * 64;
        const float* w1r1 = w1r0 + 8 * 64;
#pragma unroll
        for (int k0 = 0; k0 < 8; k0++) {
            const uint32_t a0 = __float_as_uint(__ldg(w1r0 + k0 * 8 + r));
            const uint32_t a1 = __float_as_uint(__ldg(w1r1 + k0 * 8 + r));
            const uint32_t a2 = __float_as_uint(__ldg(w1r0 + k0 * 8 + r + 4));
            const uint32_t a3 = __float_as_uint(__ldg(w1r1 + k0 * 8 + r + 4));
            const uint32_t* bp = a1p + ((wq * 8 + k0) * 32 + lid) * 8;
            const uint4 B0 = *(const uint4*)bp;
            const uint4 B1 = *(const uint4*)(bp + 4);
            mma8(d[0], a0, a1, a2, a3, B0.x, B0.y);
            mma8(d[1], a0, a1, a2, a3, B0.z, B0.w);
            mma8(d[2], a0, a1, a2, a3, B1.x, B1.y);
            mma8(d[3], a0, a1, a2, a3, B1.z, B1.w);
        }
        // a2 scatter into L3 B-fragment layout (region B; W0p dead since prior barrier)
        const float bz0 = sB1[rb * 16 + g];
        const float bz1 = sB1[rb * 16 + g + 8];
        const int lidb = (2 * r) * 4 + (g & 3);
        const int hb   = (g >= 4) ? 1 : 0;
#pragma unroll
        for (int n = 0; n < 4; n++) {
            const int wid3 = wq * 2 + (n >> 1);
            const int jv   = (n & 1) * 2 + hb;
#pragma unroll
            for (int m = 0; m < 2; m++) {
                const float bz = (m == 0) ? bz0 : bz1;
                uint32_t* base = a2p + ((wid3 * 4 + rb * 2 + m) * 32 + lidb) * 4 + jv;
                base[0]  = __float_as_uint(eluf(d[n][2 * m] + bz));
                base[16] = __float_as_uint(eluf(d[n][2 * m + 1] + bz));  // delta=1 -> +16
            }
        }
    }
    __syncthreads();

    // ============ layer 3 (tf32): D[16][128] = W2 x a2 (A from global) ===============
    {
        uint32_t a3f[16];
#pragma unroll
        for (int k0 = 0; k0 < 4; k0++) {
            a3f[k0 * 4 + 0] = __float_as_uint(__ldg(w2 + g * 32 + k0 * 8 + r));
            a3f[k0 * 4 + 1] = __float_as_uint(__ldg(w2 + (g + 8) * 32 + k0 * 8 + r));
            a3f[k0 * 4 + 2] = __float_as_uint(__ldg(w2 + g * 32 + k0 * 8 + r + 4));
            a3f[k0 * 4 + 3] = __float_as_uint(__ldg(w2 + (g + 8) * 32 + k0 * 8 + r + 4));
        }
        float d[2][4];
#pragma unroll
        for (int n = 0; n < 2; n++) { d[n][0] = d[n][1] = d[n][2] = d[n][3] = 0.0f; }
#pragma unroll
        for (int k0 = 0; k0 < 4; k0++) {
            const uint4 B = *(const uint4*)(a2p + ((wid * 4 + k0) * 32 + lid) * 4);
            mma8(d[0], a3f[k0 * 4], a3f[k0 * 4 + 1], a3f[k0 * 4 + 2], a3f[k0 * 4 + 3], B.x, B.y);
            mma8(d[1], a3f[k0 * 4], a3f[k0 * 4 + 1], a3f[k0 * 4 + 2], a3f[k0 * 4 + 3], B.z, B.w);
        }
        // scatter a3 as f16 [px][16]
#pragma unroll
        for (int n = 0; n < 2; n++) {
            const int px0 = wid * 16 + n * 8 + 2 * r;
#pragma unroll
            for (int m = 0; m < 2; m++) {
                const float bz = sB2[g + 8 * m];
                a3h[px0 * 16 + g + 8 * m]       = __float2half(eluf(d[n][2 * m] + bz));
                a3h[(px0 + 1) * 16 + g + 8 * m] = __float2half(eluf(d[n][2 * m + 1] + bz));
            }
        }
    }
    __syncthreads();

    // ---- tail: layers 4-6 per pixel (t < 128) -> plane params ------------------------
    if (t < P) {
        float a3[16];
        {
            const __half2* ah = (const __half2*)(a3h + t * 16);
#pragma unroll
            for (int i = 0; i < 8; i++) {
                const float2 f = __half22float2(ah[i]);
                a3[2 * i] = f.x; a3[2 * i + 1] = f.y;
            }
        }
        float a4[8];
        {
            const u64* b3p = (const u64*)sB3;
            u64 acc4[4];
#pragma unroll
            for (int j = 0; j < 4; j++) acc4[j] = b3p[j];
#pragma unroll
            for (int c = 0; c < 16; c++) {
                const u64 xx = pack2(a3[c], a3[c]);
                const ulonglong2 wa = *(const ulonglong2*)(wT3 + c * 8);
                const ulonglong2 wb = *(const ulonglong2*)(wT3 + c * 8 + 4);
                acc4[0] = fma2(wa.x, xx, acc4[0]); acc4[1] = fma2(wa.y, xx, acc4[1]);
                acc4[2] = fma2(wb.x, xx, acc4[2]); acc4[3] = fma2(wb.y, xx, acc4[3]);
            }
#pragma unroll
            for (int j = 0; j < 4; j++) {
                float lo, hi; unpack2(acc4[j], lo, hi);
                a4[2 * j] = eluf(lo); a4[2 * j + 1] = eluf(hi);
            }
        }
        float a5[4];
        {
            const u64* b4p = (const u64*)sB4;
            u64 acc5[2];
            acc5[0] = b4p[0]; acc5[1] = b4p[1];
#pragma unroll
            for (int c = 0; c < 8; c++) {
                const u64 xx = pack2(a4[c], a4[c]);
                const ulonglong2 w = *(const ulonglong2*)(wT4 + c * 4);
                acc5[0] = fma2(w.x, xx, acc5[0]); acc5[1] = fma2(w.y, xx, acc5[1]);
            }
            unpack2(acc5[0], a5[0], a5[1]); unpack2(acc5[1], a5[2], a5[3]);
        }
        float y[3];
#pragma unroll
        for (int o = 0; o < 3; o++) {
            float s = sBc[o];
#pragma unroll
            for (int c = 0; c < 4; c++) s += sWc[c * 3 + o] * a5[c];
            y[o] = s;
        }
        const float theta = sigmoidf_fast(y[0]) * (PI_F / 6.0f);
        const float phi   = sigmoidf_fast(y[1]) * (PI_F * 2.0f);
        const float dist  = sigmoidf_fast(y[2]) * MAX_DEPTH;
        const float st = __sinf(theta), ct = __cosf(theta);
        const float sp = __sinf(phi),   cp = __cosf(phi);
        float nx = st * cp, ny = st * sp, nz = ct;
        const float inv = rsqrtf(nx * nx + ny * ny + nz * nz);
        pln[0 * 128 + t] = nx * inv;
        pln[1 * 128 + t] = ny * inv;
        pln[2 * 128 + t] = nz * inv;
        pln[3 * 128 + t] = dist;
    }
    __syncthreads();

    // ---- epilogue: 2 threads per pixel, 4 rows each -----------------------------------
    {
        const int px   = t >> 1;
        const int half = t & 1;
        const float nx   = pln[0 * 128 + px];
        const float ny   = pln[1 * 128 + px];
        const float nz   = pln[2 * 128 + px];
        const float dist = pln[3 * 128 + px];

        const int p  = p0 + px;
        const int bb = p / HWLO;
        const int hw = p - bb * HWLO;
        const int h  = hw / W8;
        const int w  = hw - h * W8;
        float* __restrict__ op = out + ((size_t)bb * HOUT + (size_t)h * 8) * WOUT + (size_t)w * 8;

#pragma unroll
        for (int rr = 0; rr < 4; rr++) {
            const int i = half * 4 + rr;
            const float vterm = ny * ((float)i - 3.5f) * 0.125f + nz;
            float row[8];
#pragma unroll
            for (int j = 0; j < 8; j++) {
                const float u = ((float)j - 3.5f) * 0.125f;
                row[j] = __fdividef(dist, nx * u + vterm);
            }
            float4* o4 = (float4*)(op + (size_t)i * WOUT);
            o4[0] = make_float4(row[0], row[1], row[2], row[3]);
            o4[1] = make_float4(row[4], row[5], row[6], row[7]);
        }
    }
}

extern "C" void kernel_launch(void* const* d_in, const int* in_sizes, int n_in,
                              void* d_out, int out_size) {
    const float* x  = (const float*)d_in[0];
    const float* w0 = (const float*)d_in[1];
    const float* b0 = (const float*)d_in[2];
    const float* w1 = (const float*)d_in[3];
    const float* b1 = (const float*)d_in[4];
    const float* w2 = (const float*)d_in[5];
    const float* b2 = (const float*)d_in[6];
    const float* w3 = (const float*)d_in[7];
    const float* b3 = (const float*)d_in[8];
    const float* w4 = (const float*)d_in[9];
    const float* b4 = (const float*)d_in[10];
    const float* wc = (const float*)d_in[11];
    const float* bc = (const float*)d_in[12];
    float* out = (float*)d_out;

    cudaFuncSetAttribute(lpg_mma_kernel,
                         cudaFuncAttributeMaxDynamicSharedMemorySize, SMEM_BYTES);

    lpg_mma_kernel<<<NTILES, NTHR, SMEM_BYTES>>>(x, w0, b0, w1, b1, w2, b2,
                                                 w3, b3, w4, b4, wc, bc, out);
}

// round 15
// speedup vs baseline: 1.4452x; 1.4452x over previous
#include <cuda_runtime.h>
#include <cuda_fp16.h>
#include <math.h>
#include <stdint.h>

#define NB    16
#define H8    44
#define W8    144
#define HWLO  (H8 * W8)        // 6336
#define NPIX  (NB * HWLO)      // 101376
#define HOUT  (H8 * 8)         // 352
#define WOUT  (W8 * 8)         // 1152
#define P     128              // pixels per tile
#define NTILES (NPIX / P)      // 792
#define NTHR  256
#define PI_F  3.1415926535f
#define MAX_DEPTH 81.0f

typedef unsigned long long u64;

#define XPITCH 136             // X f16-pair words / a1s,a2s f32 pitch (conflict-free)
#define W0P    68              // W0 f16-pair pitch
#define A3P    132             // a3s pitch

// ---- smem layout (float offsets) ----
// Region A (34816 B): X f16x2 [64][136] -> alias a1 f32 [64][136]
//                     -> alias pln [4][128] @0 + a3 [16][132] @512 (both after a1 dead)
#define OFF_XS    0
#define OFF_A1S   0
#define OFF_PLN   0            // 512 f
#define OFF_A3S   512          // 2112 f -> ends 2624 (inside region A)
// Region B (17408 B): W0 f16x2 [64][68] -> alias a2 f32 [32][136]
#define OFF_W0S   8704
#define OFF_A2S   8704
// tables
#define OFF_WT3   13056        // 128
#define OFF_WT4   13184        // 32
#define OFF_WC    13216        // 16
#define OFF_B0    13232        // 64
#define OFF_B1    13296        // 32
#define OFF_B2    13328        // 16
#define OFF_B3    13344        // 8
#define OFF_B4    13352        // 4
#define OFF_BC    13356        // 4
#define SMEM_FLOATS 13360
#define SMEM_BYTES  (SMEM_FLOATS * 4)   // 53440 B

// ---------------- helpers -------------------------------------------------------
__device__ __forceinline__ uint32_t h2(float lo, float hi) {
    uint32_t r; asm("cvt.rn.f16x2.f32 %0, %1, %2;" : "=r"(r) : "f"(hi), "f"(lo)); return r;
}
__device__ __forceinline__ u64 pack2(float lo, float hi) {
    u64 r; asm("mov.b64 %0, {%1, %2};" : "=l"(r) : "f"(lo), "f"(hi)); return r;
}
__device__ __forceinline__ void unpack2(u64 v, float& lo, float& hi) {
    asm("mov.b64 {%0, %1}, %2;" : "=f"(lo), "=f"(hi) : "l"(v));
}
__device__ __forceinline__ u64 fma2(u64 a, u64 b, u64 c) {
    u64 d; asm("fma.rn.f32x2 %0, %1, %2, %3;" : "=l"(d) : "l"(a), "l"(b), "l"(c));
    return d;
}
__device__ __forceinline__ float eluf(float v) {
    return fmaxf(v, 0.0f) + (__expf(fminf(v, 0.0f)) - 1.0f);
}
__device__ __forceinline__ float sigmoidf_fast(float v) {
    return __fdividef(1.0f, 1.0f + __expf(-v));
}
__device__ __forceinline__ void mma16f(float* d, uint32_t a0, uint32_t a1, uint32_t a2,
                                       uint32_t a3, uint32_t b0, uint32_t b1) {
    asm volatile(
        "mma.sync.aligned.m16n8k16.row.col.f32.f16.f16.f32 "
        "{%0,%1,%2,%3}, {%4,%5,%6,%7}, {%8,%9}, {%0,%1,%2,%3};"
        : "+f"(d[0]), "+f"(d[1]), "+f"(d[2]), "+f"(d[3])
        : "r"(a0), "r"(a1), "r"(a2), "r"(a3), "r"(b0), "r"(b1));
}
__device__ __forceinline__ void mma8(float* d, uint32_t a0, uint32_t a1, uint32_t a2,
                                     uint32_t a3, uint32_t b0, uint32_t b1) {
    asm volatile(
        "mma.sync.aligned.m16n8k8.row.col.f32.tf32.tf32.f32 "
        "{%0,%1,%2,%3}, {%4,%5,%6,%7}, {%8,%9}, {%0,%1,%2,%3};"
        : "+f"(d[0]), "+f"(d[1]), "+f"(d[2]), "+f"(d[3])
        : "r"(a0), "r"(a1), "r"(a2), "r"(a3), "r"(b0), "r"(b1));
}

// ---------------------------------- kernel ------------------------------------
__global__ __launch_bounds__(NTHR, 3) void lpg_mma_kernel(
    const float* __restrict__ x,
    const float* __restrict__ w0, const float* __restrict__ b0,
    const float* __restrict__ w1, const float* __restrict__ b1,
    const float* __restrict__ w2, const float* __restrict__ b2,
    const float* __restrict__ w3, const float* __restrict__ b3,
    const float* __restrict__ w4, const float* __restrict__ b4,
    const float* __restrict__ wc, const float* __restrict__ bc,
    float* __restrict__ out)
{
    extern __shared__ float sm[];
    uint32_t* Xsu  = (uint32_t*)(sm + OFF_XS);    // f16x2 channel pairs
    uint32_t* W0su = (uint32_t*)(sm + OFF_W0S);
    float*    a1s = sm + OFF_A1S;
    float*    a2s = sm + OFF_A2S;
    float*    a3s = sm + OFF_A3S;
    float*    pln = sm + OFF_PLN;
    float* wT3 = sm + OFF_WT3;
    float* wT4 = sm + OFF_WT4;
    float* sWc = sm + OFF_WC;
    float* sB0 = sm + OFF_B0;
    float* sB1 = sm + OFF_B1;
    float* sB2 = sm + OFF_B2;
    float* sB3 = sm + OFF_B3;
    float* sB4 = sm + OFF_B4;
    float* sBc = sm + OFF_BC;

    const int t   = threadIdx.x;
    const int wid = t >> 5;
    const int lid = t & 31;
    const int p0  = blockIdx.x * P;
    const int g   = lid >> 2;      // MMA groupID
    const int r   = lid & 3;       // MMA threadID-in-group

    // ---- stage X [128ch][128px] -> f16x2 channel-pairs [64][136] -------------------
    {
        const int q4 = t & 31;                // uint4 (= 4 pixels) index
        const int p  = p0 + 4 * q4;
        const int bb = p / HWLO;
        const int hw = p - bb * HWLO;
        const float* __restrict__ xb = x + ((size_t)bb * 128) * HWLO + hw;
        const int cp0 = t >> 5;               // pair-row base
#pragma unroll
        for (int i = 0; i < 8; i++) {
            const int cpair = cp0 + i * 8;    // 0..63
            const float4 v0 = __ldg((const float4*)(xb + (size_t)(2 * cpair) * HWLO));
            const float4 v1 = __ldg((const float4*)(xb + (size_t)(2 * cpair + 1) * HWLO));
            uint4 u;
            u.x = h2(v0.x, v1.x); u.y = h2(v0.y, v1.y);
            u.z = h2(v0.z, v1.z); u.w = h2(v0.w, v1.w);
            *(uint4*)(Xsu + cpair * XPITCH + 4 * q4) = u;
        }
    }
    // ---- stage W0 [64][128] -> f16x2 k-pairs [64][68] -------------------------------
#pragma unroll
    for (int i = 0; i < 4; i++) {
        const int j = t + i * 256;            // 0..1023
        const int o = j >> 4, q = j & 15;     // row, 4-pair block
        const float4 va = __ldg((const float4*)(w0 + o * 128 + 8 * q));
        const float4 vb = __ldg((const float4*)(w0 + o * 128 + 8 * q + 4));
        uint4 u;
        u.x = h2(va.x, va.y); u.y = h2(va.z, va.w);
        u.z = h2(vb.x, vb.y); u.w = h2(vb.z, vb.w);
        *(uint4*)(W0su + o * W0P + 4 * q) = u;
    }
    // ---- small staging ---------------------------------------------------------------
    if (t < 128) { int o = t >> 4, c = t & 15; wT3[c * 8 + o] = w3[t]; }
    if (t < 32)  { int o = t >> 3, c = t & 7;  wT4[c * 4 + o] = w4[t]; }
    if (t < 12)  { int o = t >> 2, c = t & 3;  sWc[c * 3 + o] = wc[t]; }
    if (t < 64) sB0[t] = b0[t];
    if (t < 32) sB1[t] = b1[t];
    if (t < 16) sB2[t] = b2[t];
    if (t < 8)  sB3[t] = b3[t];
    if (t < 4)  sB4[t] = b4[t];
    if (t < 3)  sBc[t] = bc[t];
    __syncthreads();

    // ============ layer 1 MMA (f16 k16): D[64][128] = W0 x X =======================
    const int mg = wid & 1;        // m-half
    const int nq = wid >> 1;       // pixel quarter
    float d0[4][4], d1[4][4];
#pragma unroll
    for (int n = 0; n < 4; n++) {
        d0[n][0] = d0[n][1] = d0[n][2] = d0[n][3] = 0.0f;
        d1[n][0] = d1[n][1] = d1[n][2] = d1[n][3] = 0.0f;
    }
    {
        const int row0 = mg * 32 + g;
        const uint32_t* A0 = W0su + row0 * W0P;
        const uint32_t* A1 = A0 + 8 * W0P;
        const uint32_t* A2 = A0 + 16 * W0P;
        const uint32_t* A3 = A0 + 24 * W0P;
#pragma unroll
        for (int kb = 0; kb < 8; kb++) {
            const int kp = kb * 8;            // pair-row base (16 channels)
            const uint32_t a00 = A0[kp + r],     a01 = A1[kp + r];
            const uint32_t a02 = A0[kp + r + 4], a03 = A1[kp + r + 4];
            const uint32_t a10 = A2[kp + r],     a11 = A3[kp + r];
            const uint32_t a12 = A2[kp + r + 4], a13 = A3[kp + r + 4];
            const uint32_t* Bk0 = Xsu + (kp + r) * XPITCH + nq * 32 + g;
            const uint32_t* Bk1 = Bk0 + 4 * XPITCH;
#pragma unroll
            for (int n = 0; n < 4; n++) {
                const uint32_t b0v = Bk0[n * 8], b1v = Bk1[n * 8];
                mma16f(d0[n], a00, a01, a02, a03, b0v, b1v);
                mma16f(d1[n], a10, a11, a12, a13, b0v, b1v);
            }
        }
    }
    __syncthreads();            // all X/W0 reads done -> a1s (alias) writable

    // bias + ELU + scatter a1 (f32)
    {
        const int row0 = mg * 32 + g;
        const float bzA = sB0[row0],      bzB = sB0[row0 + 8];
        const float bzC = sB0[row0 + 16], bzD = sB0[row0 + 24];
#pragma unroll
        for (int n = 0; n < 4; n++) {
            const int px = nq * 32 + n * 8 + 2 * r;
            *(float2*)(a1s + row0 * XPITCH + px)        = make_float2(eluf(d0[n][0] + bzA), eluf(d0[n][1] + bzA));
            *(float2*)(a1s + (row0 + 8) * XPITCH + px)  = make_float2(eluf(d0[n][2] + bzB), eluf(d0[n][3] + bzB));
            *(float2*)(a1s + (row0 + 16) * XPITCH + px) = make_float2(eluf(d1[n][0] + bzC), eluf(d1[n][1] + bzC));
            *(float2*)(a1s + (row0 + 24) * XPITCH + px) = make_float2(eluf(d1[n][2] + bzD), eluf(d1[n][3] + bzD));
        }
    }
    __syncthreads();

    // ============ layer 2 MMA (tf32): D[32][128] = W1 x a1 (A from global) ==========
    {
        const int rb = wid & 1;
        const int wq = wid >> 1;
        float d[4][4];
#pragma unroll
        for (int n = 0; n < 4; n++) { d[n][0] = d[n][1] = d[n][2] = d[n][3] = 0.0f; }
        const float* __restrict__ w1r0 = w1 + (rb * 16 + g) * 64;
        const float* __restrict__ w1r1 = w1r0 + 8 * 64;
        const uint32_t* a1u  = (const uint32_t*)a1s;
#pragma unroll
        for (int k0 = 0; k0 < 64; k0 += 8) {
            const uint32_t a0 = __float_as_uint(__ldg(w1r0 + k0 + r));
            const uint32_t a1 = __float_as_uint(__ldg(w1r1 + k0 + r));
            const uint32_t a2 = __float_as_uint(__ldg(w1r0 + k0 + r + 4));
            const uint32_t a3 = __float_as_uint(__ldg(w1r1 + k0 + r + 4));
            const uint32_t* Bk0 = a1u + (k0 + r) * XPITCH + wq * 32 + g;
            const uint32_t* Bk1 = Bk0 + 4 * XPITCH;
#pragma unroll
            for (int n = 0; n < 4; n++) mma8(d[n], a0, a1, a2, a3, Bk0[n * 8], Bk1[n * 8]);
        }
        // a2s (region B) disjoint from a1s (region A); W0 reads all fenced by the two
        // barriers above -> scatter without an extra barrier.
        const int row0 = rb * 16 + g;
        const float bz0 = sB1[row0];
        const float bz1 = sB1[row0 + 8];
#pragma unroll
        for (int n = 0; n < 4; n++) {
            const int px = wq * 32 + n * 8 + 2 * r;
            *(float2*)(a2s + row0 * XPITCH + px)       = make_float2(eluf(d[n][0] + bz0), eluf(d[n][1] + bz0));
            *(float2*)(a2s + (row0 + 8) * XPITCH + px) = make_float2(eluf(d[n][2] + bz1), eluf(d[n][3] + bz1));
        }
    }
    __syncthreads();            // a2 visible; a1 reads done -> a3s (region A) writable

    // ============ layer 3 MMA (tf32): D[16][128] = W2 x a2 (A from global) ==========
    {
        uint32_t a3f[16];
#pragma unroll
        for (int k0 = 0; k0 < 32; k0 += 8) {
            const int q = k0 >> 3;
            a3f[q * 4 + 0] = __float_as_uint(__ldg(w2 + g * 32 + k0 + r));
            a3f[q * 4 + 1] = __float_as_uint(__ldg(w2 + (g + 8) * 32 + k0 + r));
            a3f[q * 4 + 2] = __float_as_uint(__ldg(w2 + g * 32 + k0 + r + 4));
            a3f[q * 4 + 3] = __float_as_uint(__ldg(w2 + (g + 8) * 32 + k0 + r + 4));
        }
        float d[2][4];
#pragma unroll
        for (int n = 0; n < 2; n++) { d[n][0] = d[n][1] = d[n][2] = d[n][3] = 0.0f; }
        const uint32_t* a2u = (const uint32_t*)a2s;
#pragma unroll
        for (int k0 = 0; k0 < 32; k0 += 8) {
            const int q = k0 >> 3;
            const uint32_t* Bk0 = a2u + (k0 + r) * XPITCH + wid * 16 + g;
            const uint32_t* Bk1 = Bk0 + 4 * XPITCH;
#pragma unroll
            for (int n = 0; n < 2; n++)
                mma8(d[n], a3f[q * 4 + 0], a3f[q * 4 + 1], a3f[q * 4 + 2], a3f[q * 4 + 3],
                     Bk0[n * 8], Bk1[n * 8]);
        }
        const float bz0 = sB2[g];
        const float bz1 = sB2[g + 8];
#pragma unroll
        for (int n = 0; n < 2; n++) {
            const int px = wid * 16 + n * 8 + 2 * r;
            *(float2*)(a3s + g * A3P + px)       = make_float2(eluf(d[n][0] + bz0), eluf(d[n][1] + bz0));
            *(float2*)(a3s + (g + 8) * A3P + px) = make_float2(eluf(d[n][2] + bz1), eluf(d[n][3] + bz1));
        }
    }
    __syncthreads();

    // ---- tail: layers 4-6 per pixel (t < 128) -> plane params ----------------------
    if (t < P) {
        float a3[16];
#pragma unroll
        for (int c = 0; c < 16; c++) a3[c] = a3s[c * A3P + t];

        float a4[8];
        {
            const u64* b3p = (const u64*)sB3;
            u64 acc4[4];
#pragma unroll
            for (int j = 0; j < 4; j++) acc4[j] = b3p[j];
#pragma unroll
            for (int c = 0; c < 16; c++) {
                const u64 xx = pack2(a3[c], a3[c]);
                const ulonglong2 wa = *(const ulonglong2*)(wT3 + c * 8);
                const ulonglong2 wb = *(const ulonglong2*)(wT3 + c * 8 + 4);
                acc4[0] = fma2(wa.x, xx, acc4[0]); acc4[1] = fma2(wa.y, xx, acc4[1]);
                acc4[2] = fma2(wb.x, xx, acc4[2]); acc4[3] = fma2(wb.y, xx, acc4[3]);
            }
#pragma unroll
            for (int j = 0; j < 4; j++) {
                float lo, hi; unpack2(acc4[j], lo, hi);
                a4[2 * j] = eluf(lo); a4[2 * j + 1] = eluf(hi);
            }
        }
        float a5[4];
        {
            const u64* b4p = (const u64*)sB4;
            u64 acc5[2];
            acc5[0] = b4p[0]; acc5[1] = b4p[1];
#pragma unroll
            for (int c = 0; c < 8; c++) {
                const u64 xx = pack2(a4[c], a4[c]);
                const ulonglong2 w = *(const ulonglong2*)(wT4 + c * 4);
                acc5[0] = fma2(w.x, xx, acc5[0]); acc5[1] = fma2(w.y, xx, acc5[1]);
            }
            unpack2(acc5[0], a5[0], a5[1]); unpack2(acc5[1], a5[2], a5[3]);
        }
        float y[3];
#pragma unroll
        for (int o = 0; o < 3; o++) {
            float s = sBc[o];
#pragma unroll
            for (int c = 0; c < 4; c++) s += sWc[c * 3 + o] * a5[c];
            y[o] = s;
        }
        const float theta = sigmoidf_fast(y[0]) * (PI_F / 6.0f);
        const float phi   = sigmoidf_fast(y[1]) * (PI_F * 2.0f);
        const float dist  = sigmoidf_fast(y[2]) * MAX_DEPTH;
        const float st = __sinf(theta), ct = __cosf(theta);
        const float sp = __sinf(phi),   cp = __cosf(phi);
        float nx = st * cp, ny = st * sp, nz = ct;
        const float inv = rsqrtf(nx * nx + ny * ny + nz * nz);
        pln[0 * 128 + t] = nx * inv;
        pln[1 * 128 + t] = ny * inv;
        pln[2 * 128 + t] = nz * inv;
        pln[3 * 128 + t] = dist;
    }
    __syncthreads();

    // ---- epilogue: 2 threads per pixel, 4 rows each ---------------------------------
    {
        const int px   = t >> 1;
        const int half = t & 1;
        const float nx   = pln[0 * 128 + px];
        const float ny   = pln[1 * 128 + px];
        const float nz   = pln[2 * 128 + px];
        const float dist = pln[3 * 128 + px];

        const int p  = p0 + px;
        const int bb = p / HWLO;
        const int hw = p - bb * HWLO;
        const int h  = hw / W8;
        const int w  = hw - h * W8;
        float* __restrict__ op = out + ((size_t)bb * HOUT + (size_t)h * 8) * WOUT + (size_t)w * 8;

#pragma unroll
        for (int rr = 0; rr < 4; rr++) {
            const int i = half * 4 + rr;
            const float vterm = ny * ((float)i - 3.5f) * 0.125f + nz;
            float row[8];
#pragma unroll
            for (int j = 0; j < 8; j++) {
                const float u = ((float)j - 3.5f) * 0.125f;
                row[j] = __fdividef(dist, nx * u + vterm);
            }
            float4* o4 = (float4*)(op + (size_t)i * WOUT);
            o4[0] = make_float4(row[0], row[1], row[2], row[3]);
            o4[1] = make_float4(row[4], row[5], row[6], row[7]);
        }
    }
}

extern "C" void kernel_launch(void* const* d_in, const int* in_sizes, int n_in,
                              void* d_out, int out_size) {
    const float* x  = (const float*)d_in[0];
    const float* w0 = (const float*)d_in[1];
    const float* b0 = (const float*)d_in[2];
    const float* w1 = (const float*)d_in[3];
    const float* b1 = (const float*)d_in[4];
    const float* w2 = (const float*)d_in[5];
    const float* b2 = (const float*)d_in[6];
    const float* w3 = (const float*)d_in[7];
    const float* b3 = (const float*)d_in[8];
    const float* w4 = (const float*)d_in[9];
    const float* b4 = (const float*)d_in[10];
    const float* wc = (const float*)d_in[11];
    const float* bc = (const float*)d_in[12];
    float* out = (float*)d_out;

    cudaFuncSetAttribute(lpg_mma_kernel,
                         cudaFuncAttributeMaxDynamicSharedMemorySize, SMEM_BYTES);

    lpg_mma_kernel<<<NTILES, NTHR, SMEM_BYTES>>>(x, w0, b0, w1, b1, w2, b2,
                                                 w3, b3, w4, b4, wc, bc, out);
}

// round 16
// speedup vs baseline: 1.6231x; 1.1231x over previous
#include <cuda_runtime.h>
#include <cuda_fp16.h>
#include <math.h>
#include <stdint.h>

#define NB    16
#define H8    44
#define W8    144
#define HWLO  (H8 * W8)        // 6336
#define NPIX  (NB * HWLO)      // 101376
#define HOUT  (H8 * 8)         // 352
#define WOUT  (W8 * 8)         // 1152
#define P     128              // pixels per tile
#define NTILES (NPIX / P)      // 792
#define NTHR  256
#define PI_F  3.1415926535f
#define MAX_DEPTH 81.0f

typedef unsigned long long u64;

#define XPITCH 136             // X f16-pair words / a1s,a2s f32 pitch (conflict-free)
#define W0P    68              // W0 f16-pair pitch (272B rows -> ldmatrix conflict-free)
#define W1P    68              // W1 f32 pitch (272B rows -> ldmatrix conflict-free)
#define A3P    132             // a3s pitch

// ---- smem layout (float offsets) — exactly R13 ----
#define OFF_XS    0            // X f16x2 [64][136] u32 = 8704
#define OFF_A1S   0            // alias: a1 f32 [64][136]
#define OFF_PLN   0            // alias: [4][128] (a1 dead)
#define OFF_W0S   8704         // W0 f16x2 [64][68] u32 = 4352
#define OFF_A2S   8704         // alias: a2 f32 [32][136] (W0 dead)
#define OFF_W1S   13056        // W1 f32 [32][68] = 2176
#define OFF_A3S   13056        // alias: a3 f32 [16][132] (W1 dead)
#define OFF_WT3   15232        // 128
#define OFF_WT4   15360        // 32
#define OFF_WC    15392        // 16
#define OFF_B0    15408        // 64
#define OFF_B1    15472        // 32
#define OFF_B2    15504        // 16
#define OFF_B3    15520        // 8
#define OFF_B4    15528        // 4
#define OFF_BC    15532        // 4
#define SMEM_FLOATS 15536
#define SMEM_BYTES  (SMEM_FLOATS * 4)   // 62144 B -> 3 CTAs/SM

// ---------------- helpers -------------------------------------------------------
__device__ __forceinline__ uint32_t smem_u32(const void* p) {
    uint32_t a;
    asm("{ .reg .u64 t; cvta.to.shared.u64 t, %1; cvt.u32.u64 %0, t; }" : "=r"(a) : "l"(p));
    return a;
}
__device__ __forceinline__ void cp_async16(uint32_t dst, const void* src) {
    asm volatile("cp.async.cg.shared.global [%0], [%1], 16;" :: "r"(dst), "l"(src));
}
#define CP_COMMIT() asm volatile("cp.async.commit_group;" ::: "memory")
#define CP_WAIT(N)  asm volatile("cp.async.wait_group %0;" :: "n"(N) : "memory")

__device__ __forceinline__ uint32_t h2(float lo, float hi) {
    uint32_t r; asm("cvt.rn.f16x2.f32 %0, %1, %2;" : "=r"(r) : "f"(hi), "f"(lo)); return r;
}
__device__ __forceinline__ u64 pack2(float lo, float hi) {
    u64 r; asm("mov.b64 %0, {%1, %2};" : "=l"(r) : "f"(lo), "f"(hi)); return r;
}
__device__ __forceinline__ void unpack2(u64 v, float& lo, float& hi) {
    asm("mov.b64 {%0, %1}, %2;" : "=f"(lo), "=f"(hi) : "l"(v));
}
__device__ __forceinline__ u64 fma2(u64 a, u64 b, u64 c) {
    u64 d; asm("fma.rn.f32x2 %0, %1, %2, %3;" : "=l"(d) : "l"(a), "l"(b), "l"(c));
    return d;
}
__device__ __forceinline__ float eluf(float v) {
    return fmaxf(v, 0.0f) + (__expf(fminf(v, 0.0f)) - 1.0f);
}
__device__ __forceinline__ float sigmoidf_fast(float v) {
    return __fdividef(1.0f, 1.0f + __expf(-v));
}
__device__ __forceinline__ void ldm4(uint32_t& r0, uint32_t& r1, uint32_t& r2,
                                     uint32_t& r3, uint32_t addr) {
    asm volatile("ldmatrix.sync.aligned.m8n8.x4.shared.b16 {%0,%1,%2,%3}, [%4];"
                 : "=r"(r0), "=r"(r1), "=r"(r2), "=r"(r3) : "r"(addr));
}
__device__ __forceinline__ void mma16f(float* d, uint32_t a0, uint32_t a1, uint32_t a2,
                                       uint32_t a3, uint32_t b0, uint32_t b1) {
    asm volatile(
        "mma.sync.aligned.m16n8k16.row.col.f32.f16.f16.f32 "
        "{%0,%1,%2,%3}, {%4,%5,%6,%7}, {%8,%9}, {%0,%1,%2,%3};"
        : "+f"(d[0]), "+f"(d[1]), "+f"(d[2]), "+f"(d[3])
        : "r"(a0), "r"(a1), "r"(a2), "r"(a3), "r"(b0), "r"(b1));
}
__device__ __forceinline__ void mma8(float* d, uint32_t a0, uint32_t a1, uint32_t a2,
                                     uint32_t a3, uint32_t b0, uint32_t b1) {
    asm volatile(
        "mma.sync.aligned.m16n8k8.row.col.f32.tf32.tf32.f32 "
        "{%0,%1,%2,%3}, {%4,%5,%6,%7}, {%8,%9}, {%0,%1,%2,%3};"
        : "+f"(d[0]), "+f"(d[1]), "+f"(d[2]), "+f"(d[3])
        : "r"(a0), "r"(a1), "r"(a2), "r"(a3), "r"(b0), "r"(b1));
}

// ---------------------------------- kernel ------------------------------------
__global__ __launch_bounds__(NTHR, 3) void lpg_mma_kernel(
    const float* __restrict__ x,
    const float* __restrict__ w0, const float* __restrict__ b0,
    const float* __restrict__ w1, const float* __restrict__ b1,
    const float* __restrict__ w2, const float* __restrict__ b2,
    const float* __restrict__ w3, const float* __restrict__ b3,
    const float* __restrict__ w4, const float* __restrict__ b4,
    const float* __restrict__ wc, const float* __restrict__ bc,
    float* __restrict__ out)
{
    extern __shared__ float sm[];
    uint32_t* Xsu  = (uint32_t*)(sm + OFF_XS);    // f16x2 channel pairs
    uint32_t* W0su = (uint32_t*)(sm + OFF_W0S);
    float*    a1s = sm + OFF_A1S;
    float*    a2s = sm + OFF_A2S;
    float*    a3s = sm + OFF_A3S;
    float*    pln = sm + OFF_PLN;
    float* wT3 = sm + OFF_WT3;
    float* wT4 = sm + OFF_WT4;
    float* sWc = sm + OFF_WC;
    float* sB0 = sm + OFF_B0;
    float* sB1 = sm + OFF_B1;
    float* sB2 = sm + OFF_B2;
    float* sB3 = sm + OFF_B3;
    float* sB4 = sm + OFF_B4;
    float* sBc = sm + OFF_BC;

    const int t   = threadIdx.x;
    const int wid = t >> 5;
    const int lid = t & 31;
    const int p0  = blockIdx.x * P;
    const int g   = lid >> 2;      // MMA groupID
    const int r   = lid & 3;       // MMA threadID-in-group

    const uint32_t sbase = smem_u32(sm);

    // ---- W1 via cp.async (raw f32 -> tf32 ops read top bits) ----------------------
#pragma unroll
    for (int i = 0; i < 2; i++) {
        const int j = t + i * 256;            // 0..511 float4
        const int o = j >> 4, cq = j & 15;
        cp_async16(sbase + (uint32_t)((OFF_W1S + o * W1P + cq * 4) * 4),
                   w1 + o * 64 + cq * 4);
    }
    CP_COMMIT();

    // ---- stage X [128ch][128px] -> f16x2 channel-pairs [64][136] -------------------
    {
        const int q4 = t & 31;                // uint4 (= 4 pixels) index
        const int p  = p0 + 4 * q4;
        const int bb = p / HWLO;
        const int hw = p - bb * HWLO;
        const float* __restrict__ xb = x + ((size_t)bb * 128) * HWLO + hw;
        const int cp0 = t >> 5;               // pair-row base
#pragma unroll
        for (int i = 0; i < 8; i++) {
            const int cpair = cp0 + i * 8;    // 0..63
            const float4 v0 = __ldg((const float4*)(xb + (size_t)(2 * cpair) * HWLO));
            const float4 v1 = __ldg((const float4*)(xb + (size_t)(2 * cpair + 1) * HWLO));
            uint4 u;
            u.x = h2(v0.x, v1.x); u.y = h2(v0.y, v1.y);
            u.z = h2(v0.z, v1.z); u.w = h2(v0.w, v1.w);
            *(uint4*)(Xsu + cpair * XPITCH + 4 * q4) = u;
        }
    }
    // ---- stage W0 [64][128] -> f16x2 k-pairs [64][68] -------------------------------
#pragma unroll
    for (int i = 0; i < 4; i++) {
        const int j = t + i * 256;            // 0..1023
        const int o = j >> 4, q = j & 15;     // row, 4-pair block
        const float4 va = __ldg((const float4*)(w0 + o * 128 + 8 * q));
        const float4 vb = __ldg((const float4*)(w0 + o * 128 + 8 * q + 4));
        uint4 u;
        u.x = h2(va.x, va.y); u.y = h2(va.z, va.w);
        u.z = h2(vb.x, vb.y); u.w = h2(vb.z, vb.w);
        *(uint4*)(W0su + o * W0P + 4 * q) = u;
    }
    // ---- small staging ---------------------------------------------------------------
    if (t < 128) { int o = t >> 4, c = t & 15; wT3[c * 8 + o] = w3[t]; }
    if (t < 32)  { int o = t >> 3, c = t & 7;  wT4[c * 4 + o] = w4[t]; }
    if (t < 12)  { int o = t >> 2, c = t & 3;  sWc[c * 3 + o] = wc[t]; }
    if (t < 64) sB0[t] = b0[t];
    if (t < 32) sB1[t] = b1[t];
    if (t < 16) sB2[t] = b2[t];
    if (t < 8)  sB3[t] = b3[t];
    if (t < 4)  sB4[t] = b4[t];
    if (t < 3)  sBc[t] = bc[t];

    CP_WAIT(0);
    __syncthreads();

    // ============ layer 1 MMA (f16 k16): D[64][128] = W0 x X =======================
    const int mg = wid & 1;        // m-half
    const int nq = wid >> 1;       // pixel quarter
    float d0[4][4], d1[4][4];
#pragma unroll
    for (int n = 0; n < 4; n++) {
        d0[n][0] = d0[n][1] = d0[n][2] = d0[n][3] = 0.0f;
        d1[n][0] = d1[n][1] = d1[n][2] = d1[n][3] = 0.0f;
    }
    {
        // ldmatrix lane address: row = mg*32 + (lid&15) (+16 for tile 1),
        // u32 col offset = (lid>>4)*4, advancing 8 u32 (32 B) per kb.
        const uint32_t w0addr0 = sbase + (uint32_t)((OFF_W0S +
                               (mg * 32 + (lid & 15)) * W0P + (lid >> 4) * 4) * 4);
        const uint32_t w0addr1 = w0addr0 + (uint32_t)(16 * W0P * 4);
#pragma unroll
        for (int kb = 0; kb < 8; kb++) {
            const int kp = kb * 8;            // pair-row base (16 channels)
            uint32_t a00, a01, a02, a03, a10, a11, a12, a13;
            ldm4(a00, a01, a02, a03, w0addr0 + kb * 32);
            ldm4(a10, a11, a12, a13, w0addr1 + kb * 32);
            const uint32_t* Bk0 = Xsu + (kp + r) * XPITCH + nq * 32 + g;
            const uint32_t* Bk1 = Bk0 + 4 * XPITCH;
#pragma unroll
            for (int n = 0; n < 4; n++) {
                const uint32_t b0v = Bk0[n * 8], b1v = Bk1[n * 8];
                mma16f(d0[n], a00, a01, a02, a03, b0v, b1v);
                mma16f(d1[n], a10, a11, a12, a13, b0v, b1v);
            }
        }
    }
    __syncthreads();            // all X/W0 reads done -> a1s (alias) writable

    // bias + ELU + scatter a1 (f32)
    {
        const int row0 = mg * 32 + g;
        const float bzA = sB0[row0],      bzB = sB0[row0 + 8];
        const float bzC = sB0[row0 + 16], bzD = sB0[row0 + 24];
#pragma unroll
        for (int n = 0; n < 4; n++) {
            const int px = nq * 32 + n * 8 + 2 * r;
            *(float2*)(a1s + row0 * XPITCH + px)        = make_float2(eluf(d0[n][0] + bzA), eluf(d0[n][1] + bzA));
            *(float2*)(a1s + (row0 + 8) * XPITCH + px)  = make_float2(eluf(d0[n][2] + bzB), eluf(d0[n][3] + bzB));
            *(float2*)(a1s + (row0 + 16) * XPITCH + px) = make_float2(eluf(d1[n][0] + bzC), eluf(d1[n][1] + bzC));
            *(float2*)(a1s + (row0 + 24) * XPITCH + px) = make_float2(eluf(d1[n][2] + bzD), eluf(d1[n][3] + bzD));
        }
    }
    __syncthreads();

    // ============ layer 2 MMA (tf32): D[32][128] = W1 x a1 ==========================
    {
        const int rb = wid & 1;
        const int wq = wid >> 1;
        float d[4][4];
#pragma unroll
        for (int n = 0; n < 4; n++) { d[n][0] = d[n][1] = d[n][2] = d[n][3] = 0.0f; }
        // tf32-as-2xb16 ldmatrix: row = rb*16 + (lid&15); byte extra = (lid>>4)*16
        const uint32_t w1addr = sbase + (uint32_t)((OFF_W1S +
                              (rb * 16 + (lid & 15)) * W1P + (lid >> 4) * 4) * 4);
        const uint32_t* a1u = (const uint32_t*)a1s;
#pragma unroll
        for (int k0 = 0; k0 < 64; k0 += 8) {
            uint32_t a0, a1, a2, a3;
            ldm4(a0, a1, a2, a3, w1addr + k0 * 4);
            const uint32_t* Bk0 = a1u + (k0 + r) * XPITCH + wq * 32 + g;
            const uint32_t* Bk1 = Bk0 + 4 * XPITCH;
#pragma unroll
            for (int n = 0; n < 4; n++) mma8(d[n], a0, a1, a2, a3, Bk0[n * 8], Bk1[n * 8]);
        }
        // a2s (region B) disjoint from a1s; W0 reads fenced two barriers ago.
        // The next __syncthreads (below) orders all W1 reads before L3's a3 writes.
        const int row0 = rb * 16 + g;
        const float bz0 = sB1[row0];
        const float bz1 = sB1[row0 + 8];
#pragma unroll
        for (int n = 0; n < 4; n++) {
            const int px = wq * 32 + n * 8 + 2 * r;
            *(float2*)(a2s + row0 * XPITCH + px)       = make_float2(eluf(d[n][0] + bz0), eluf(d[n][1] + bz0));
            *(float2*)(a2s + (row0 + 8) * XPITCH + px) = make_float2(eluf(d[n][2] + bz1), eluf(d[n][3] + bz1));
        }
    }
    __syncthreads();

    // ============ layer 3 MMA (tf32): D[16][128] = W2 x a2 (A from global) ==========
    {
        uint32_t a3f[16];
#pragma unroll
        for (int k0 = 0; k0 < 32; k0 += 8) {
            const int q = k0 >> 3;
            a3f[q * 4 + 0] = __float_as_uint(__ldg(w2 + g * 32 + k0 + r));
            a3f[q * 4 + 1] = __float_as_uint(__ldg(w2 + (g + 8) * 32 + k0 + r));
            a3f[q * 4 + 2] = __float_as_uint(__ldg(w2 + g * 32 + k0 + r + 4));
            a3f[q * 4 + 3] = __float_as_uint(__ldg(w2 + (g + 8) * 32 + k0 + r + 4));
        }
        float d[2][4];
#pragma unroll
        for (int n = 0; n < 2; n++) { d[n][0] = d[n][1] = d[n][2] = d[n][3] = 0.0f; }
        const uint32_t* a2u = (const uint32_t*)a2s;
#pragma unroll
        for (int k0 = 0; k0 < 32; k0 += 8) {
            const int q = k0 >> 3;
            const uint32_t* Bk0 = a2u + (k0 + r) * XPITCH + wid * 16 + g;
            const uint32_t* Bk1 = Bk0 + 4 * XPITCH;
#pragma unroll
            for (int n = 0; n < 2; n++)
                mma8(d[n], a3f[q * 4 + 0], a3f[q * 4 + 1], a3f[q * 4 + 2], a3f[q * 4 + 3],
                     Bk0[n * 8], Bk1[n * 8]);
        }
        const float bz0 = sB2[g];
        const float bz1 = sB2[g + 8];
#pragma unroll
        for (int n = 0; n < 2; n++) {
            const int px = wid * 16 + n * 8 + 2 * r;
            *(float2*)(a3s + g * A3P + px)       = make_float2(eluf(d[n][0] + bz0), eluf(d[n][1] + bz0));
            *(float2*)(a3s + (g + 8) * A3P + px) = make_float2(eluf(d[n][2] + bz1), eluf(d[n][3] + bz1));
        }
    }
    __syncthreads();

    // ---- tail: layers 4-6 per pixel (t < 128) -> plane params ----------------------
    if (t < P) {
        float a3[16];
#pragma unroll
        for (int c = 0; c < 16; c++) a3[c] = a3s[c * A3P + t];

        float a4[8];
        {
            const u64* b3p = (const u64*)sB3;
            u64 acc4[4];
#pragma unroll
            for (int j = 0; j < 4; j++) acc4[j] = b3p[j];
#pragma unroll
            for (int c = 0; c < 16; c++) {
                const u64 xx = pack2(a3[c], a3[c]);
                const ulonglong2 wa = *(const ulonglong2*)(wT3 + c * 8);
                const ulonglong2 wb = *(const ulonglong2*)(wT3 + c * 8 + 4);
                acc4[0] = fma2(wa.x, xx, acc4[0]); acc4[1] = fma2(wa.y, xx, acc4[1]);
                acc4[2] = fma2(wb.x, xx, acc4[2]); acc4[3] = fma2(wb.y, xx, acc4[3]);
            }
#pragma unroll
            for (int j = 0; j < 4; j++) {
                float lo, hi; unpack2(acc4[j], lo, hi);
                a4[2 * j] = eluf(lo); a4[2 * j + 1] = eluf(hi);
            }
        }
        float a5[4];
        {
            const u64* b4p = (const u64*)sB4;
            u64 acc5[2];
            acc5[0] = b4p[0]; acc5[1] = b4p[1];
#pragma unroll
            for (int c = 0; c < 8; c++) {
                const u64 xx = pack2(a4[c], a4[c]);
                const ulonglong2 w = *(const ulonglong2*)(wT4 + c * 4);
                acc5[0] = fma2(w.x, xx, acc5[0]); acc5[1] = fma2(w.y, xx, acc5[1]);
            }
            unpack2(acc5[0], a5[0], a5[1]); unpack2(acc5[1], a5[2], a5[3]);
        }
        float y[3];
#pragma unroll
        for (int o = 0; o < 3; o++) {
            float s = sBc[o];
#pragma unroll
            for (int c = 0; c < 4; c++) s += sWc[c * 3 + o] * a5[c];
            y[o] = s;
        }
        const float theta = sigmoidf_fast(y[0]) * (PI_F / 6.0f);
        const float phi   = sigmoidf_fast(y[1]) * (PI_F * 2.0f);
        const float dist  = sigmoidf_fast(y[2]) * MAX_DEPTH;
        const float st = __sinf(theta), ct = __cosf(theta);
        const float sp = __sinf(phi),   cp = __cosf(phi);
        float nx = st * cp, ny = st * sp, nz = ct;
        const float inv = rsqrtf(nx * nx + ny * ny + nz * nz);
        pln[0 * 128 + t] = nx * inv;
        pln[1 * 128 + t] = ny * inv;
        pln[2 * 128 + t] = nz * inv;
        pln[3 * 128 + t] = dist;
    }
    __syncthreads();

    // ---- epilogue: 2 threads per pixel, 4 rows each ---------------------------------
    {
        const int px   = t >> 1;
        const int half = t & 1;
        const float nx   = pln[0 * 128 + px];
        const float ny   = pln[1 * 128 + px];
        const float nz   = pln[2 * 128 + px];
        const float dist = pln[3 * 128 + px];

        const int p  = p0 + px;
        const int bb = p / HWLO;
        const int hw = p - bb * HWLO;
        const int h  = hw / W8;
        const int w  = hw - h * W8;
        float* __restrict__ op = out + ((size_t)bb * HOUT + (size_t)h * 8) * WOUT + (size_t)w * 8;

#pragma unroll
        for (int rr = 0; rr < 4; rr++) {
            const int i = half * 4 + rr;
            const float vterm = ny * ((float)i - 3.5f) * 0.125f + nz;
            float row[8];
#pragma unroll
            for (int j = 0; j < 8; j++) {
                const float u = ((float)j - 3.5f) * 0.125f;
                row[j] = __fdividef(dist, nx * u + vterm);
            }
            float4* o4 = (float4*)(op + (size_t)i * WOUT);
            o4[0] = make_float4(row[0], row[1], row[2], row[3]);
            o4[1] = make_float4(row[4], row[5], row[6], row[7]);
        }
    }
}

extern "C" void kernel_launch(void* const* d_in, const int* in_sizes, int n_in,
                              void* d_out, int out_size) {
    const float* x  = (const float*)d_in[0];
    const float* w0 = (const float*)d_in[1];
    const float* b0 = (const float*)d_in[2];
    const float* w1 = (const float*)d_in[3];
    const float* b1 = (const float*)d_in[4];
    const float* w2 = (const float*)d_in[5];
    const float* b2 = (const float*)d_in[6];
    const float* w3 = (const float*)d_in[7];
    const float* b3 = (const float*)d_in[8];
    const float* w4 = (const float*)d_in[9];
    const float* b4 = (const float*)d_in[10];
    const float* wc = (const float*)d_in[11];
    const float* bc = (const float*)d_in[12];
    float* out = (float*)d_out;

    cudaFuncSetAttribute(lpg_mma_kernel,
                         cudaFuncAttributeMaxDynamicSharedMemorySize, SMEM_BYTES);

    lpg_mma_kernel<<<NTILES, NTHR, SMEM_BYTES>>>(x, w0, b0, w1, b1, w2, b2,
                                                 w3, b3, w4, b4, wc, bc, out);
}

// round 17
// speedup vs baseline: 1.7547x; 1.0811x over previous
#include <cuda_runtime.h>
#include <cuda_fp16.h>
#include <math.h>
#include <stdint.h>

#define NB    16
#define H8    44
#define W8    144
#define HWLO  (H8 * W8)        // 6336
#define NPIX  (NB * HWLO)      // 101376
#define HOUT  (H8 * 8)         // 352
#define WOUT  (W8 * 8)         // 1152
#define P     128              // pixels per tile
#define NTILES (NPIX / P)      // 792
#define NTHR  256
#define PI_F  3.1415926535f
#define MAX_DEPTH 81.0f

typedef unsigned long long u64;

#define XPITCH 136             // u32 pitch: Xsu / a1h / a2h pair-rows (conflict-free)
#define W0P    68              // W0 f16-pair pitch (272B rows, ldmatrix conflict-free)
#define W1P    36              // W1 f16-pair pitch (144B rows, ldmatrix conflict-free)
#define A3P    132             // a3s f32 pitch

// ---- smem layout (4-byte offsets) ----
// Region A: Xsu u32 [64][136] = 8704  -> alias a1h u32 [32][136] = 4352 @0
//                                     -> a3s f32 [16][132] = 2112 @4352 (disjoint from a1h)
#define OFF_XS    0
#define OFF_A1H   0
#define OFF_A3S   4352
// Region B: W0 u32 [64][68] = 4352 -> alias a2h u32 [16][136] = 2176 (W0 dead)
#define OFF_W0S   8704
#define OFF_A2H   8704
#define OFF_W1S   13056        // u32 [32][36] = 1152 -> 14208
#define OFF_WT3   14208        // 128
#define OFF_WT4   14336        // 32
#define OFF_WC    14368        // 16
#define OFF_B0    14384        // 64
#define OFF_B1    14448        // 32
#define OFF_B2    14480        // 16
#define OFF_B3    14496        // 8
#define OFF_B4    14504        // 4
#define OFF_BC    14508        // 4
#define SMEM_FLOATS 14512
#define SMEM_BYTES  (SMEM_FLOATS * 4)   // 58048 B -> 3 CTAs/SM

// ---------------- helpers -------------------------------------------------------
__device__ __forceinline__ uint32_t smem_u32(const void* p) {
    uint32_t a;
    asm("{ .reg .u64 t; cvta.to.shared.u64 t, %1; cvt.u32.u64 %0, t; }" : "=r"(a) : "l"(p));
    return a;
}
__device__ __forceinline__ uint32_t h2(float lo, float hi) {
    uint32_t r; asm("cvt.rn.f16x2.f32 %0, %1, %2;" : "=r"(r) : "f"(hi), "f"(lo)); return r;
}
__device__ __forceinline__ u64 pack2(float lo, float hi) {
    u64 r; asm("mov.b64 %0, {%1, %2};" : "=l"(r) : "f"(lo), "f"(hi)); return r;
}
__device__ __forceinline__ void unpack2(u64 v, float& lo, float& hi) {
    asm("mov.b64 {%0, %1}, %2;" : "=f"(lo), "=f"(hi) : "l"(v));
}
__device__ __forceinline__ u64 fma2(u64 a, u64 b, u64 c) {
    u64 d; asm("fma.rn.f32x2 %0, %1, %2, %3;" : "=l"(d) : "l"(a), "l"(b), "l"(c));
    return d;
}
__device__ __forceinline__ float eluf(float v) {
    return fmaxf(v, 0.0f) + (__expf(fminf(v, 0.0f)) - 1.0f);
}
__device__ __forceinline__ float sigmoidf_fast(float v) {
    return __fdividef(1.0f, 1.0f + __expf(-v));
}
__device__ __forceinline__ void ldm4(uint32_t& r0, uint32_t& r1, uint32_t& r2,
                                     uint32_t& r3, uint32_t addr) {
    asm volatile("ldmatrix.sync.aligned.m8n8.x4.shared.b16 {%0,%1,%2,%3}, [%4];"
                 : "=r"(r0), "=r"(r1), "=r"(r2), "=r"(r3) : "r"(addr));
}
__device__ __forceinline__ void mma16f(float* d, uint32_t a0, uint32_t a1, uint32_t a2,
                                       uint32_t a3, uint32_t b0, uint32_t b1) {
    asm volatile(
        "mma.sync.aligned.m16n8k16.row.col.f32.f16.f16.f32 "
        "{%0,%1,%2,%3}, {%4,%5,%6,%7}, {%8,%9}, {%0,%1,%2,%3};"
        : "+f"(d[0]), "+f"(d[1]), "+f"(d[2]), "+f"(d[3])
        : "r"(a0), "r"(a1), "r"(a2), "r"(a3), "r"(b0), "r"(b1));
}

// ---------------------------------- kernel ------------------------------------
__global__ __launch_bounds__(NTHR, 3) void lpg_mma_kernel(
    const float* __restrict__ x,
    const float* __restrict__ w0, const float* __restrict__ b0,
    const float* __restrict__ w1, const float* __restrict__ b1,
    const float* __restrict__ w2, const float* __restrict__ b2,
    const float* __restrict__ w3, const float* __restrict__ b3,
    const float* __restrict__ w4, const float* __restrict__ b4,
    const float* __restrict__ wc, const float* __restrict__ bc,
    float* __restrict__ out)
{
    extern __shared__ float sm[];
    uint32_t* Xsu  = (uint32_t*)(sm + OFF_XS);    // f16x2 channel pairs
    uint32_t* W0su = (uint32_t*)(sm + OFF_W0S);   // permuted rows, f16x2 k-pairs
    uint32_t* W1su = (uint32_t*)(sm + OFF_W1S);   // permuted rows, f16x2 k-pairs
    uint32_t* a1h  = (uint32_t*)(sm + OFF_A1H);   // [32 pair][136]
    uint32_t* a2h  = (uint32_t*)(sm + OFF_A2H);   // [16 pair][136]
    float*    a3s  = sm + OFF_A3S;                // [16][132]
    float* wT3 = sm + OFF_WT3;
    float* wT4 = sm + OFF_WT4;
    float* sWc = sm + OFF_WC;
    float* sB0 = sm + OFF_B0;
    float* sB1 = sm + OFF_B1;
    float* sB2 = sm + OFF_B2;
    float* sB3 = sm + OFF_B3;
    float* sB4 = sm + OFF_B4;
    float* sBc = sm + OFF_BC;

    const int t   = threadIdx.x;
    const int wid = t >> 5;
    const int lid = t & 31;
    const int p0  = blockIdx.x * P;
    const int g   = lid >> 2;      // MMA groupID
    const int r   = lid & 3;       // MMA threadID-in-group

    const uint32_t sbase = smem_u32(sm);

    // ---- stage X [128ch][128px] -> f16x2 channel-pairs [64][136] (natural order) --
    {
        const int q4 = t & 31;
        const int p  = p0 + 4 * q4;
        const int bb = p / HWLO;
        const int hw = p - bb * HWLO;
        const float* __restrict__ xb = x + ((size_t)bb * 128) * HWLO + hw;
        const int cp0 = t >> 5;
#pragma unroll
        for (int i = 0; i < 8; i++) {
            const int cpair = cp0 + i * 8;
            const float4 v0 = __ldg((const float4*)(xb + (size_t)(2 * cpair) * HWLO));
            const float4 v1 = __ldg((const float4*)(xb + (size_t)(2 * cpair + 1) * HWLO));
            uint4 u;
            u.x = h2(v0.x, v1.x); u.y = h2(v0.y, v1.y);
            u.z = h2(v0.z, v1.z); u.w = h2(v0.w, v1.w);
            *(uint4*)(Xsu + cpair * XPITCH + 4 * q4) = u;
        }
    }
    // ---- stage W0 permuted: smem row (mg*32+b*16+s) <- channel mg*32+b*16+perm(s) --
#pragma unroll
    for (int i = 0; i < 4; i++) {
        const int j = t + i * 256;            // 0..1023: 64 rows x 16 uint4
        const int o = j >> 4, q = j & 15;
        const int mgs = o >> 5, rem = o & 31, bbt = (rem >> 4) & 1, s = rem & 15;
        const int ch = mgs * 32 + bbt * 16 + ((s < 8) ? 2 * s : 2 * (s - 8) + 1);
        const float4 va = __ldg((const float4*)(w0 + ch * 128 + 8 * q));
        const float4 vb = __ldg((const float4*)(w0 + ch * 128 + 8 * q + 4));
        uint4 u;
        u.x = h2(va.x, va.y); u.y = h2(va.z, va.w);
        u.z = h2(vb.x, vb.y); u.w = h2(vb.z, vb.w);
        *(uint4*)(W0su + o * W0P + 4 * q) = u;
    }
    // ---- stage W1 permuted f16: 32 rows x 8 uint4 = 256 (1/thread) ----------------
    {
        const int o = t >> 3, q = t & 7;      // row, uint4 (8 k)
        const int rbt = o >> 4, s = o & 15;
        const int ch = rbt * 16 + ((s < 8) ? 2 * s : 2 * (s - 8) + 1);
        const float* src = w1 + ch * 64 + q * 8;
        const float4 va = __ldg((const float4*)src);
        const float4 vb = __ldg((const float4*)(src + 4));
        uint4 u;
        u.x = h2(va.x, va.y); u.y = h2(va.z, va.w);
        u.z = h2(vb.x, vb.y); u.w = h2(vb.z, vb.w);
        *(uint4*)(W1su + o * W1P + 4 * q) = u;
    }
    // ---- small staging -------------------------------------------------------------
    if (t < 128) { int o = t >> 4, c = t & 15; wT3[c * 8 + o] = w3[t]; }
    if (t < 32)  { int o = t >> 3, c = t & 7;  wT4[c * 4 + o] = w4[t]; }
    if (t < 12)  { int o = t >> 2, c = t & 3;  sWc[c * 3 + o] = wc[t]; }
    if (t < 64) sB0[t] = b0[t];
    if (t < 32) sB1[t] = b1[t];
    if (t < 16) sB2[t] = b2[t];
    if (t < 8)  sB3[t] = b3[t];
    if (t < 4)  sB4[t] = b4[t];
    if (t < 3)  sBc[t] = bc[t];
    __syncthreads();                                   // B1

    // ============ layer 1 (f16 k16): D[64][128] = W0 x X ============================
    const int mg = wid & 1;        // m-half (32 rows)
    const int nq = wid >> 1;       // pixel quarter
    float d0[4][4], d1[4][4];
#pragma unroll
    for (int n = 0; n < 4; n++) {
        d0[n][0] = d0[n][1] = d0[n][2] = d0[n][3] = 0.0f;
        d1[n][0] = d1[n][1] = d1[n][2] = d1[n][3] = 0.0f;
    }
    {
        const uint32_t w0addr0 = sbase + (uint32_t)((OFF_W0S +
                               (mg * 32 + (lid & 15)) * W0P + (lid >> 4) * 4) * 4);
        const uint32_t w0addr1 = w0addr0 + (uint32_t)(16 * W0P * 4);
#pragma unroll
        for (int kb = 0; kb < 8; kb++) {
            const int kp = kb * 8;
            uint32_t a00, a01, a02, a03, a10, a11, a12, a13;
            ldm4(a00, a01, a02, a03, w0addr0 + kb * 32);
            ldm4(a10, a11, a12, a13, w0addr1 + kb * 32);
            const uint32_t* Bk0 = Xsu + (kp + r) * XPITCH + nq * 32 + g;
            const uint32_t* Bk1 = Bk0 + 4 * XPITCH;
#pragma unroll
            for (int n = 0; n < 4; n++) {
                const uint32_t b0v = Bk0[n * 8], b1v = Bk1[n * 8];
                mma16f(d0[n], a00, a01, a02, a03, b0v, b1v);
                mma16f(d1[n], a10, a11, a12, a13, b0v, b1v);
            }
        }
    }
    __syncthreads();               // B2: X/W0 reads done -> a1h (alias) writable

    // ---- a1 scatter: packed f16x2 channel-pairs (rows permuted so d0 = pair) -------
    {
        // tile0 rows (g, g+8) = channels mg*32 + (2g, 2g+1) -> pair row mg*16+g
        // tile1 rows          = channels mg*32+16 + (2g,2g+1) -> pair row mg*16+8+g
        const float bz00 = sB0[mg * 32 + 2 * g],      bz01 = sB0[mg * 32 + 2 * g + 1];
        const float bz10 = sB0[mg * 32 + 16 + 2 * g], bz11 = sB0[mg * 32 + 16 + 2 * g + 1];
        uint32_t* row0 = a1h + (mg * 16 + g) * XPITCH;
        uint32_t* row1 = a1h + (mg * 16 + 8 + g) * XPITCH;
#pragma unroll
        for (int n = 0; n < 4; n++) {
            const int px = nq * 32 + n * 8 + 2 * r;
            uint2 u0, u1;
            u0.x = h2(eluf(d0[n][0] + bz00), eluf(d0[n][2] + bz01));
            u0.y = h2(eluf(d0[n][1] + bz00), eluf(d0[n][3] + bz01));
            u1.x = h2(eluf(d1[n][0] + bz10), eluf(d1[n][2] + bz11));
            u1.y = h2(eluf(d1[n][1] + bz10), eluf(d1[n][3] + bz11));
            *(uint2*)(row0 + px) = u0;
            *(uint2*)(row1 + px) = u1;
        }
    }
    __syncthreads();               // B3

    // ============ layer 2 (f16 k16): D[32][128] = W1 x a1 ===========================
    {
        const int rb = wid & 1;
        const int wq = wid >> 1;
        float d[4][4];
#pragma unroll
        for (int n = 0; n < 4; n++) { d[n][0] = d[n][1] = d[n][2] = d[n][3] = 0.0f; }
        const uint32_t w1addr = sbase + (uint32_t)((OFF_W1S +
                              (rb * 16 + (lid & 15)) * W1P + (lid >> 4) * 4) * 4);
#pragma unroll
        for (int kb = 0; kb < 4; kb++) {
            uint32_t a0, a1, a2, a3;
            ldm4(a0, a1, a2, a3, w1addr + kb * 32);   // 8 u32 = 32 B per k16
            const uint32_t* Bk0 = a1h + (kb * 8 + r) * XPITCH + wq * 32 + g;
            const uint32_t* Bk1 = Bk0 + 4 * XPITCH;
#pragma unroll
            for (int n = 0; n < 4; n++) mma16f(d[n], a0, a1, a2, a3, Bk0[n * 8], Bk1[n * 8]);
        }
        // a2 scatter: pair row rb*8+g, channels rb*16 + (2g, 2g+1)
        const float bz0 = sB1[rb * 16 + 2 * g];
        const float bz1 = sB1[rb * 16 + 2 * g + 1];
        uint32_t* row = a2h + (rb * 8 + g) * XPITCH;
#pragma unroll
        for (int n = 0; n < 4; n++) {
            const int px = wq * 32 + n * 8 + 2 * r;
            uint2 u;
            u.x = h2(eluf(d[n][0] + bz0), eluf(d[n][2] + bz1));
            u.y = h2(eluf(d[n][1] + bz0), eluf(d[n][3] + bz1));
            *(uint2*)(row + px) = u;
        }
    }
    __syncthreads();               // B4

    // ============ layer 3 (f16 k16): D[16][128] = W2 x a2 (A from global) ===========
    {
        uint32_t af[8];
#pragma unroll
        for (int kb = 0; kb < 2; kb++) {
            const int kp = kb * 8;
            const float2 v0 = *(const float2*)(w2 + g * 32 + 2 * (kp + r));
            const float2 v1 = *(const float2*)(w2 + (g + 8) * 32 + 2 * (kp + r));
            const float2 v2 = *(const float2*)(w2 + g * 32 + 2 * (kp + r + 4));
            const float2 v3 = *(const float2*)(w2 + (g + 8) * 32 + 2 * (kp + r + 4));
            af[kb * 4 + 0] = h2(v0.x, v0.y);
            af[kb * 4 + 1] = h2(v1.x, v1.y);
            af[kb * 4 + 2] = h2(v2.x, v2.y);
            af[kb * 4 + 3] = h2(v3.x, v3.y);
        }
        float d[2][4];
#pragma unroll
        for (int n = 0; n < 2; n++) { d[n][0] = d[n][1] = d[n][2] = d[n][3] = 0.0f; }
#pragma unroll
        for (int kb = 0; kb < 2; kb++) {
            const uint32_t* Bk0 = a2h + (kb * 8 + r) * XPITCH + wid * 16 + g;
            const uint32_t* Bk1 = Bk0 + 4 * XPITCH;
#pragma unroll
            for (int n = 0; n < 2; n++)
                mma16f(d[n], af[kb * 4 + 0], af[kb * 4 + 1], af[kb * 4 + 2], af[kb * 4 + 3],
                       Bk0[n * 8], Bk1[n * 8]);
        }
        // a3 scatter (f32, natural rows)
        const float bz0 = sB2[g];
        const float bz1 = sB2[g + 8];
#pragma unroll
        for (int n = 0; n < 2; n++) {
            const int px = wid * 16 + n * 8 + 2 * r;
            *(float2*)(a3s + g * A3P + px)       = make_float2(eluf(d[n][0] + bz0), eluf(d[n][1] + bz0));
            *(float2*)(a3s + (g + 8) * A3P + px) = make_float2(eluf(d[n][2] + bz1), eluf(d[n][3] + bz1));
        }
    }
    __syncthreads();               // B5

    // ---- tail (2 threads/pixel, redundant) + epilogue: no extra barrier -------------
    {
        const int px   = t >> 1;
        const int half = t & 1;

        float a3[16];
#pragma unroll
        for (int c = 0; c < 16; c++) a3[c] = a3s[c * A3P + px];

        float a4[8];
        {
            const u64* b3p = (const u64*)sB3;
            u64 acc4[4];
#pragma unroll
            for (int j = 0; j < 4; j++) acc4[j] = b3p[j];
#pragma unroll
            for (int c = 0; c < 16; c++) {
                const u64 xx = pack2(a3[c], a3[c]);
                const ulonglong2 wa = *(const ulonglong2*)(wT3 + c * 8);
                const ulonglong2 wb = *(const ulonglong2*)(wT3 + c * 8 + 4);
                acc4[0] = fma2(wa.x, xx, acc4[0]); acc4[1] = fma2(wa.y, xx, acc4[1]);
                acc4[2] = fma2(wb.x, xx, acc4[2]); acc4[3] = fma2(wb.y, xx, acc4[3]);
            }
#pragma unroll
            for (int j = 0; j < 4; j++) {
                float lo, hi; unpack2(acc4[j], lo, hi);
                a4[2 * j] = eluf(lo); a4[2 * j + 1] = eluf(hi);
            }
        }
        float a5[4];
        {
            const u64* b4p = (const u64*)sB4;
            u64 acc5[2];
            acc5[0] = b4p[0]; acc5[1] = b4p[1];
#pragma unroll
            for (int c = 0; c < 8; c++) {
                const u64 xx = pack2(a4[c], a4[c]);
                const ulonglong2 w = *(const ulonglong2*)(wT4 + c * 4);
                acc5[0] = fma2(w.x, xx, acc5[0]); acc5[1] = fma2(w.y, xx, acc5[1]);
            }
            unpack2(acc5[0], a5[0], a5[1]); unpack2(acc5[1], a5[2], a5[3]);
        }
        float y[3];
#pragma unroll
        for (int o = 0; o < 3; o++) {
            float s = sBc[o];
#pragma unroll
            for (int c = 0; c < 4; c++) s += sWc[c * 3 + o] * a5[c];
            y[o] = s;
        }
        const float theta = sigmoidf_fast(y[0]) * (PI_F / 6.0f);
        const float phi   = sigmoidf_fast(y[1]) * (PI_F * 2.0f);
        const float dist  = sigmoidf_fast(y[2]) * MAX_DEPTH;
        const float st = __sinf(theta), ct = __cosf(theta);
        const float sp = __sinf(phi),   cp = __cosf(phi);
        float nx = st * cp, ny = st * sp, nz = ct;
        const float inv = rsqrtf(nx * nx + ny * ny + nz * nz);
        nx *= inv; ny *= inv; nz *= inv;

        const int p  = p0 + px;
        const int bb = p / HWLO;
        const int hw = p - bb * HWLO;
        const int h  = hw / W8;
        const int w  = hw - h * W8;
        float* __restrict__ op = out + ((size_t)bb * HOUT + (size_t)h * 8) * WOUT + (size_t)w * 8;

#pragma unroll
        for (int rr = 0; rr < 4; rr++) {
            const int i = half * 4 + rr;
            const float vterm = ny * ((float)i - 3.5f) * 0.125f + nz;
            float row[8];
#pragma unroll
            for (int j = 0; j < 8; j++) {
                const float u = ((float)j - 3.5f) * 0.125f;
                row[j] = __fdividef(dist, nx * u + vterm);
            }
            float4* o4 = (float4*)(op + (size_t)i * WOUT);
            o4[0] = make_float4(row[0], row[1], row[2], row[3]);
            o4[1] = make_float4(row[4], row[5], row[6], row[7]);
        }
    }
}

extern "C" void kernel_launch(void* const* d_in, const int* in_sizes, int n_in,
                              void* d_out, int out_size) {
    const float* x  = (const float*)d_in[0];
    const float* w0 = (const float*)d_in[1];
    const float* b0 = (const float*)d_in[2];
    const float* w1 = (const float*)d_in[3];
    const float* b1 = (const float*)d_in[4];
    const float* w2 = (const float*)d_in[5];
    const float* b2 = (const float*)d_in[6];
    const float* w3 = (const float*)d_in[7];
    const float* b3 = (const float*)d_in[8];
    const float* w4 = (const float*)d_in[9];
    const float* b4 = (const float*)d_in[10];
    const float* wc = (const float*)d_in[11];
    const float* bc = (const float*)d_in[12];
    float* out = (float*)d_out;

    cudaFuncSetAttribute(lpg_mma_kernel,
                         cudaFuncAttributeMaxDynamicSharedMemorySize, SMEM_BYTES);

    lpg_mma_kernel<<<NTILES, NTHR, SMEM_BYTES>>>(x, w0, b0, w1, b1, w2, b2,
                                                 w3, b3, w4, b4, wc, bc, out);
}